// round 1
// baseline (speedup 1.0000x reference)
#include <cuda_runtime.h>
#include <math.h>

// Problem constants
#define BSZ   1024
#define KDIM  256     // F == H == 256, all GEMMs are 1024x256x256
#define NPTS  128
#define SSZ   2
#define LOG2PI_F 1.8378770664093453f
#define LOG1P_HALF 0.40546510810816438f

// Output layout (flattened tuple, in order):
// sampled (S*N, B, 2) = 524288 | genLoss (B,N) 131072 | realLoss 131072 |
// lossA 131072 | lossB (B,N,S) 262144
#define OFF_SAMPLED 0
#define OFF_GEN     524288
#define OFF_REAL    655360
#define OFF_LOSSA   786432
#define OFF_LOSSB   917504

// Scratch (device globals: no allocation allowed)
__device__ float g_bufA[BSZ * KDIM];
__device__ float g_bufB[BSZ * KDIM];
__device__ float g_mu[BSZ * KDIM];     // (B, N, 2) flattened
__device__ float g_WpT[KDIM * 256];    // Wp transposed to [H][n*2+k]

// ---------------------------------------------------------------------------
// Transpose Wp (N,H,2) -> WpT[h][n*2+k]
// ---------------------------------------------------------------------------
__global__ __launch_bounds__(256) void transpose_wp_kernel(const float* __restrict__ Wp,
                                                           float* __restrict__ WpT) {
    int idx = blockIdx.x * 256 + threadIdx.x;   // 0..65535
    int h = idx >> 8;
    int col = idx & 255;                        // col = n*2 + k
    WpT[idx] = Wp[(col >> 1) * 512 + h * 2 + (col & 1)];
}

// ---------------------------------------------------------------------------
// fp32 GEMM: C[1024,256] = act(A[1024,256] @ W[256,256] + bias + addc)
// Tile 64x64, BK=16, 256 threads, 4x4 per thread.
// ---------------------------------------------------------------------------
__global__ __launch_bounds__(256) void gemm_kernel(
    const float* __restrict__ A, const float* __restrict__ W,
    const float* __restrict__ bias, float* __restrict__ C,
    int doRelu, float addc)
{
    const int Nn = 256, K = 256;
    __shared__ __align__(16) float As[16][68];  // transposed: As[k][row], padded
    __shared__ __align__(16) float Ws[16][64];

    const int t  = threadIdx.x;
    const int m0 = blockIdx.y * 64;
    const int n0 = blockIdx.x * 64;
    const int tx = t & 15;
    const int ty = t >> 4;

    float acc[4][4] = {};

    const int ar  = t >> 2;   // 0..63 : A row within tile
    const int akq = t & 3;    // 0..3  : which float4 of the 16-wide k slab
    const int wkr = t >> 4;   // 0..15 : W k row
    const int wnc = t & 15;   // 0..15 : W col quad

    for (int kk = 0; kk < K; kk += 16) {
        float4 av = *(const float4*)&A[(m0 + ar) * K + kk + akq * 4];
        As[akq * 4 + 0][ar] = av.x;
        As[akq * 4 + 1][ar] = av.y;
        As[akq * 4 + 2][ar] = av.z;
        As[akq * 4 + 3][ar] = av.w;
        *(float4*)&Ws[wkr][wnc * 4] =
            *(const float4*)&W[(kk + wkr) * Nn + n0 + wnc * 4];
        __syncthreads();

        #pragma unroll
        for (int k = 0; k < 16; k++) {
            float4 a4 = *(const float4*)&As[k][ty * 4];
            float4 b4 = *(const float4*)&Ws[k][tx * 4];
            float aa[4] = {a4.x, a4.y, a4.z, a4.w};
            float bb[4] = {b4.x, b4.y, b4.z, b4.w};
            #pragma unroll
            for (int i = 0; i < 4; i++)
                #pragma unroll
                for (int j = 0; j < 4; j++)
                    acc[i][j] = fmaf(aa[i], bb[j], acc[i][j]);
        }
        __syncthreads();
    }

    float4 bv = *(const float4*)&bias[n0 + tx * 4];
    float bb[4] = {bv.x + addc, bv.y + addc, bv.z + addc, bv.w + addc};
    #pragma unroll
    for (int i = 0; i < 4; i++) {
        float4 v;
        v.x = acc[i][0] + bb[0];
        v.y = acc[i][1] + bb[1];
        v.z = acc[i][2] + bb[2];
        v.w = acc[i][3] + bb[3];
        if (doRelu) {
            v.x = fmaxf(v.x, 0.0f); v.y = fmaxf(v.y, 0.0f);
            v.z = fmaxf(v.z, 0.0f); v.w = fmaxf(v.w, 0.0f);
        }
        *(float4*)&C[(m0 + ty * 4 + i) * Nn + n0 + tx * 4] = v;
    }
}

// ---------------------------------------------------------------------------
// Fused tail: one CTA per batch row b; thread = (n, s), tid = 2n + s.
// Computes sampled, realLoss, lossA, lossB, genLoss.
// ---------------------------------------------------------------------------
__global__ __launch_bounds__(256) void tail_kernel(
    const float* __restrict__ realPoints,
    const float* __restrict__ predMu,
    const float* __restrict__ predScale,
    const float* __restrict__ eps,
    float* __restrict__ out)
{
    const int b = blockIdx.x;
    __shared__ float mu_s[256];      // (n,k)
    __shared__ float am[128];        // -0.5/dev_m^2
    __shared__ float cm[128];        // -2*log(dev_m) - LOG2PI
    __shared__ float sc[7];          // r0 r1 pm0 pm1 ips0 ips1 logpsum

    const int tid = threadIdx.x;
    mu_s[tid] = g_mu[b * 256 + tid];
    if (tid < 128) {
        float dev = 0.001f + (float)tid * (0.009f / 127.0f);
        am[tid] = -0.5f / (dev * dev);
        cm[tid] = -2.0f * logf(dev) - LOG2PI_F;
    }
    if (tid == 0) {
        sc[0] = realPoints[b * 2];
        sc[1] = realPoints[b * 2 + 1];
        sc[2] = predMu[b * 2];
        sc[3] = predMu[b * 2 + 1];
        float p0 = predScale[b * 2], p1 = predScale[b * 2 + 1];
        sc[4] = 1.0f / p0;
        sc[5] = 1.0f / p1;
        sc[6] = logf(p0) + logf(p1);
    }
    __syncthreads();

    const int n = tid >> 1;
    const int s = tid & 1;

    const float mu0 = mu_s[2 * n];
    const float mu1 = mu_s[2 * n + 1];
    const float dev = 0.001f + (float)n * (0.009f / 127.0f);

    const int eoff = s * (BSZ * NPTS * 2) + (b * NPTS + n) * 2;
    const float e0 = eps[eoff];
    const float e1 = eps[eoff + 1];
    const float s0 = fmaf(dev, e0, mu0);
    const float s1 = fmaf(dev, e1, mu1);

    // sampled[(s*128+n), b, :]
    {
        long so = ((long)(s * NPTS + n) * BSZ + b) * 2;
        out[OFF_SAMPLED + so]     = s0;
        out[OFF_SAMPLED + so + 1] = s1;
    }

    // lossB: softmax over m of logprob(sampled | mu_m, dev_m), pick diag m=n
    float sumexp = 0.0f;
    float en = 0.0f;
    #pragma unroll 4
    for (int m = 0; m < 128; m++) {
        float d0 = s0 - mu_s[2 * m];
        float d1 = s1 - mu_s[2 * m + 1];
        float ss = fmaf(d0, d0, d1 * d1);
        float lb = fmaf(ss, am[m], cm[m]);
        float e  = __expf(lb);        // lb <= ~12.5: no overflow; lb_n >= ~-30: no underflow
        sumexp += e;
        if (m == n) en = e;
    }
    float diag = en / sumexp;
    float lbv  = 1.0f - diag;
    out[OFF_LOSSB + b * 256 + tid] = lbv * lbv;   // (b, n, s), tid = 2n+s

    // logprob of sampled under predicted dist (shared by lossA and genLoss)
    float z0 = (s0 - sc[2]) * sc[4];
    float z1 = (s1 - sc[3]) * sc[5];
    float lp = fmaf(-0.5f, fmaf(z0, z0, z1 * z1), -sc[6] - LOG2PI_F);
    float gl  = 1.0f / (1.0f + __expf(-lp));   // sigmoid(lp)
    float sgn = 1.0f / (1.0f + __expf(lp));    // sigmoid(-lp)
    float tA  = LOG1P_HALF - log1pf(sgn);
    tA *= tA;

    // combine the two s-samples (partner lane is tid^1)
    float gl_o = __shfl_xor_sync(0xffffffffu, gl, 1);
    float tA_o = __shfl_xor_sync(0xffffffffu, tA, 1);

    if (s == 0) {
        float glm   = 0.5f * (gl + gl_o);
        float lossA = 0.5f * (tA + tA_o);
        // realLoss
        float dr0 = sc[0] - mu0;
        float dr1 = sc[1] - mu1;
        float ssr = fmaf(dr0, dr0, dr1 * dr1);
        float rlp = fmaf(ssr, am[n], cm[n]);
        float rl  = 1.0f / (1.0f + __expf(-rlp));
        out[OFF_REAL  + b * NPTS + n] = rl;
        out[OFF_LOSSA + b * NPTS + n] = lossA;
        out[OFF_GEN   + b * NPTS + n] = glm * (1.0f - rl);
    }
}

// ---------------------------------------------------------------------------
extern "C" void kernel_launch(void* const* d_in, const int* in_sizes, int n_in,
                              void* d_out, int out_size) {
    const float* latents    = (const float*)d_in[0];
    const float* realPoints = (const float*)d_in[1];
    const float* predMu     = (const float*)d_in[2];
    const float* predScale  = (const float*)d_in[3];
    const float* eps        = (const float*)d_in[4];
    const float* W[5]  = {(const float*)d_in[5],  (const float*)d_in[7],
                          (const float*)d_in[9],  (const float*)d_in[11],
                          (const float*)d_in[13]};
    const float* bb[5] = {(const float*)d_in[6],  (const float*)d_in[8],
                          (const float*)d_in[10], (const float*)d_in[12],
                          (const float*)d_in[14]};
    const float* Wp = (const float*)d_in[15];
    const float* bp = (const float*)d_in[16];
    float* out = (float*)d_out;

    float *bufA, *bufB, *mu, *WpT;
    cudaGetSymbolAddress((void**)&bufA, g_bufA);
    cudaGetSymbolAddress((void**)&bufB, g_bufB);
    cudaGetSymbolAddress((void**)&mu,   g_mu);
    cudaGetSymbolAddress((void**)&WpT,  g_WpT);

    transpose_wp_kernel<<<256, 256>>>(Wp, WpT);

    dim3 ggrid(4, 16);   // (N/64, M/64)
    // 5 hidden layers with relu, ping-pong buffers
    gemm_kernel<<<ggrid, 256>>>(latents, W[0], bb[0], bufA, 1, 0.0f);
    gemm_kernel<<<ggrid, 256>>>(bufA,    W[1], bb[1], bufB, 1, 0.0f);
    gemm_kernel<<<ggrid, 256>>>(bufB,    W[2], bb[2], bufA, 1, 0.0f);
    gemm_kernel<<<ggrid, 256>>>(bufA,    W[3], bb[3], bufB, 1, 0.0f);
    gemm_kernel<<<ggrid, 256>>>(bufB,    W[4], bb[4], bufA, 1, 0.0f);
    // projection: mu = 0.5 + h @ WpT + bp
    gemm_kernel<<<ggrid, 256>>>(bufA, WpT, bp, mu, 0, 0.5f);

    tail_kernel<<<BSZ, 256>>>(realPoints, predMu, predScale, eps, out);
}

// round 2
// speedup vs baseline: 1.5056x; 1.5056x over previous
#include <cuda_runtime.h>
#include <math.h>

// Problem constants
#define BSZ   1024
#define KDIM  256
#define NPTS  128
#define SSZ   2
#define LOG2PI_F 1.8378770664093453f
#define LOG1P_HALF 0.40546510810816438f

// Output layout offsets
#define OFF_SAMPLED 0
#define OFF_GEN     524288
#define OFF_REAL    655360
#define OFF_LOSSA   786432
#define OFF_LOSSB   917504

// GEMM tiling
#define BM 32
#define BN 64
#define BK 32
#define NSLAB (KDIM / BK)

// Scratch (device globals: no allocation allowed)
__device__ float g_bufA[BSZ * KDIM];
__device__ float g_bufB[BSZ * KDIM];
__device__ float g_mu[BSZ * KDIM];     // (B, N, 2) flattened
__device__ float g_WpT[KDIM * 256];    // Wp transposed to [H][n*2+k]

// ---------------------------------------------------------------------------
// Transpose Wp (N,H,2) -> WpT[h][n*2+k]
// ---------------------------------------------------------------------------
__global__ __launch_bounds__(256) void transpose_wp_kernel(const float* __restrict__ Wp,
                                                           float* __restrict__ WpT) {
    int idx = blockIdx.x * 256 + threadIdx.x;   // 0..65535
    int h = idx >> 8;
    int col = idx & 255;                        // col = n*2 + k
    WpT[idx] = Wp[(col >> 1) * 512 + h * 2 + (col & 1)];
}

// ---------------------------------------------------------------------------
// fp32 GEMM: C[1024,256] = act(A[1024,256] @ W[256,256] + bias + addc)
// Tile 32x64, BK=32, 128 threads, 4x4 micro-tile, double-buffered smem,
// software-pipelined global loads. Grid = (256/64, 1024/32) = (4, 32) = 128 CTAs.
// ---------------------------------------------------------------------------
__global__ __launch_bounds__(128) void gemm_kernel(
    const float* __restrict__ A, const float* __restrict__ W,
    const float* __restrict__ bias, float* __restrict__ C,
    int doRelu, float addc)
{
    __shared__ __align__(16) float As[2][BK][BM + 4];  // k-major, pad 36 (16B aligned rows)
    __shared__ __align__(16) float Ws[2][BK][BN];

    const int t  = threadIdx.x;
    const int m0 = blockIdx.y * BM;
    const int n0 = blockIdx.x * BN;
    const int tx = t & 15;      // n quad (0..15)
    const int ty = t >> 4;      // m quad (0..7)

    // A load mapping: thread loads A[m0+ar][aq*4 ..] and [aq*4+16 ..]
    const int ar = t >> 2;      // 0..31
    const int aq = t & 3;       // 0..3
    // W load mapping: 4 passes of 8 rows
    const int wr = t >> 4;      // 0..7
    const int wc = t & 15;      // 0..15

    float acc[4][4] = {};
    float4 aReg0, aReg1, wReg[4];

    const float* Arow = &A[(m0 + ar) * KDIM];

    // prefetch slab 0
    aReg0 = *(const float4*)(Arow + aq * 4);
    aReg1 = *(const float4*)(Arow + aq * 4 + 16);
#pragma unroll
    for (int p = 0; p < 4; p++)
        wReg[p] = *(const float4*)&W[(wr + p * 8) * 256 + n0 + wc * 4];

    // store slab 0
    {
        float* a0 = (float*)&aReg0;
        float* a1 = (float*)&aReg1;
#pragma unroll
        for (int j = 0; j < 4; j++) As[0][aq * 4 + j][ar]      = a0[j];
#pragma unroll
        for (int j = 0; j < 4; j++) As[0][aq * 4 + 16 + j][ar] = a1[j];
#pragma unroll
        for (int p = 0; p < 4; p++) *(float4*)&Ws[0][wr + p * 8][wc * 4] = wReg[p];
    }
    __syncthreads();

#pragma unroll 1
    for (int s = 0; s < NSLAB; s++) {
        const int cur = s & 1;
        if (s < NSLAB - 1) {
            const int kk = (s + 1) * BK;
            aReg0 = *(const float4*)(Arow + kk + aq * 4);
            aReg1 = *(const float4*)(Arow + kk + aq * 4 + 16);
#pragma unroll
            for (int p = 0; p < 4; p++)
                wReg[p] = *(const float4*)&W[(kk + wr + p * 8) * 256 + n0 + wc * 4];
        }

#pragma unroll
        for (int k = 0; k < BK; k++) {
            float4 a4 = *(const float4*)&As[cur][k][ty * 4];
            float4 b4 = *(const float4*)&Ws[cur][k][tx * 4];
            float aa[4] = {a4.x, a4.y, a4.z, a4.w};
            float bb[4] = {b4.x, b4.y, b4.z, b4.w};
#pragma unroll
            for (int i = 0; i < 4; i++)
#pragma unroll
                for (int j = 0; j < 4; j++)
                    acc[i][j] = fmaf(aa[i], bb[j], acc[i][j]);
        }

        if (s < NSLAB - 1) {
            const int nxt = cur ^ 1;
            __syncthreads();   // everyone done reading buffer nxt (slab s-1)
            float* a0 = (float*)&aReg0;
            float* a1 = (float*)&aReg1;
#pragma unroll
            for (int j = 0; j < 4; j++) As[nxt][aq * 4 + j][ar]      = a0[j];
#pragma unroll
            for (int j = 0; j < 4; j++) As[nxt][aq * 4 + 16 + j][ar] = a1[j];
#pragma unroll
            for (int p = 0; p < 4; p++) *(float4*)&Ws[nxt][wr + p * 8][wc * 4] = wReg[p];
            __syncthreads();   // buffer nxt ready
        }
    }

    float4 bv = *(const float4*)&bias[n0 + tx * 4];
    float bb[4] = {bv.x + addc, bv.y + addc, bv.z + addc, bv.w + addc};
#pragma unroll
    for (int i = 0; i < 4; i++) {
        float4 v;
        v.x = acc[i][0] + bb[0];
        v.y = acc[i][1] + bb[1];
        v.z = acc[i][2] + bb[2];
        v.w = acc[i][3] + bb[3];
        if (doRelu) {
            v.x = fmaxf(v.x, 0.0f); v.y = fmaxf(v.y, 0.0f);
            v.z = fmaxf(v.z, 0.0f); v.w = fmaxf(v.w, 0.0f);
        }
        *(float4*)&C[(m0 + ty * 4 + i) * 256 + n0 + tx * 4] = v;
    }
}

// ---------------------------------------------------------------------------
// Fused tail: one CTA per batch row b; thread = (n, s), tid = 2n + s.
// ---------------------------------------------------------------------------
__global__ __launch_bounds__(256) void tail_kernel(
    const float* __restrict__ realPoints,
    const float* __restrict__ predMu,
    const float* __restrict__ predScale,
    const float* __restrict__ eps,
    float* __restrict__ out)
{
    const int b = blockIdx.x;
    __shared__ float mu_s[256];      // (n,k)
    __shared__ float am[128];        // -0.5/dev_m^2
    __shared__ float cm[128];        // -2*log(dev_m) - LOG2PI
    __shared__ float sc[7];          // r0 r1 pm0 pm1 ips0 ips1 logpsum

    const int tid = threadIdx.x;
    mu_s[tid] = g_mu[b * 256 + tid];
    if (tid < 128) {
        float dev = 0.001f + (float)tid * (0.009f / 127.0f);
        am[tid] = -0.5f / (dev * dev);
        cm[tid] = -2.0f * logf(dev) - LOG2PI_F;
    }
    if (tid == 0) {
        sc[0] = realPoints[b * 2];
        sc[1] = realPoints[b * 2 + 1];
        sc[2] = predMu[b * 2];
        sc[3] = predMu[b * 2 + 1];
        float p0 = predScale[b * 2], p1 = predScale[b * 2 + 1];
        sc[4] = 1.0f / p0;
        sc[5] = 1.0f / p1;
        sc[6] = logf(p0) + logf(p1);
    }
    __syncthreads();

    const int n = tid >> 1;
    const int s = tid & 1;

    const float mu0 = mu_s[2 * n];
    const float mu1 = mu_s[2 * n + 1];
    const float dev = 0.001f + (float)n * (0.009f / 127.0f);

    const int eoff = s * (BSZ * NPTS * 2) + (b * NPTS + n) * 2;
    const float e0 = eps[eoff];
    const float e1 = eps[eoff + 1];
    const float s0 = fmaf(dev, e0, mu0);
    const float s1 = fmaf(dev, e1, mu1);

    {
        long so = ((long)(s * NPTS + n) * BSZ + b) * 2;
        out[OFF_SAMPLED + so]     = s0;
        out[OFF_SAMPLED + so + 1] = s1;
    }

    // lossB: softmax over m, pick diag m=n
    float sumexp = 0.0f;
    float en = 0.0f;
#pragma unroll 4
    for (int m = 0; m < 128; m++) {
        float d0 = s0 - mu_s[2 * m];
        float d1 = s1 - mu_s[2 * m + 1];
        float ss = fmaf(d0, d0, d1 * d1);
        float lb = fmaf(ss, am[m], cm[m]);
        float e  = __expf(lb);
        sumexp += e;
        if (m == n) en = e;
    }
    float diag = en / sumexp;
    float lbv  = 1.0f - diag;
    out[OFF_LOSSB + b * 256 + tid] = lbv * lbv;

    float z0 = (s0 - sc[2]) * sc[4];
    float z1 = (s1 - sc[3]) * sc[5];
    float lp = fmaf(-0.5f, fmaf(z0, z0, z1 * z1), -sc[6] - LOG2PI_F);
    float gl  = 1.0f / (1.0f + __expf(-lp));
    float sgn = 1.0f / (1.0f + __expf(lp));
    float tA  = LOG1P_HALF - log1pf(sgn);
    tA *= tA;

    float gl_o = __shfl_xor_sync(0xffffffffu, gl, 1);
    float tA_o = __shfl_xor_sync(0xffffffffu, tA, 1);

    if (s == 0) {
        float glm   = 0.5f * (gl + gl_o);
        float lossA = 0.5f * (tA + tA_o);
        float dr0 = sc[0] - mu0;
        float dr1 = sc[1] - mu1;
        float ssr = fmaf(dr0, dr0, dr1 * dr1);
        float rlp = fmaf(ssr, am[n], cm[n]);
        float rl  = 1.0f / (1.0f + __expf(-rlp));
        out[OFF_REAL  + b * NPTS + n] = rl;
        out[OFF_LOSSA + b * NPTS + n] = lossA;
        out[OFF_GEN   + b * NPTS + n] = glm * (1.0f - rl);
    }
}

// ---------------------------------------------------------------------------
extern "C" void kernel_launch(void* const* d_in, const int* in_sizes, int n_in,
                              void* d_out, int out_size) {
    const float* latents    = (const float*)d_in[0];
    const float* realPoints = (const float*)d_in[1];
    const float* predMu     = (const float*)d_in[2];
    const float* predScale  = (const float*)d_in[3];
    const float* eps        = (const float*)d_in[4];
    const float* W[5]  = {(const float*)d_in[5],  (const float*)d_in[7],
                          (const float*)d_in[9],  (const float*)d_in[11],
                          (const float*)d_in[13]};
    const float* bb[5] = {(const float*)d_in[6],  (const float*)d_in[8],
                          (const float*)d_in[10], (const float*)d_in[12],
                          (const float*)d_in[14]};
    const float* Wp = (const float*)d_in[15];
    const float* bp = (const float*)d_in[16];
    float* out = (float*)d_out;

    float *bufA, *bufB, *mu, *WpT;
    cudaGetSymbolAddress((void**)&bufA, g_bufA);
    cudaGetSymbolAddress((void**)&bufB, g_bufB);
    cudaGetSymbolAddress((void**)&mu,   g_mu);
    cudaGetSymbolAddress((void**)&WpT,  g_WpT);

    transpose_wp_kernel<<<256, 256>>>(Wp, WpT);

    dim3 ggrid(KDIM / BN, BSZ / BM);   // (4, 32) = 128 CTAs
    gemm_kernel<<<ggrid, 128>>>(latents, W[0], bb[0], bufA, 1, 0.0f);
    gemm_kernel<<<ggrid, 128>>>(bufA,    W[1], bb[1], bufB, 1, 0.0f);
    gemm_kernel<<<ggrid, 128>>>(bufB,    W[2], bb[2], bufA, 1, 0.0f);
    gemm_kernel<<<ggrid, 128>>>(bufA,    W[3], bb[3], bufB, 1, 0.0f);
    gemm_kernel<<<ggrid, 128>>>(bufB,    W[4], bb[4], bufA, 1, 0.0f);
    gemm_kernel<<<ggrid, 128>>>(bufA, WpT, bp, mu, 0, 0.5f);

    tail_kernel<<<BSZ, 256>>>(realPoints, predMu, predScale, eps, out);
}